// round 1
// baseline (speedup 1.0000x reference)
#include <cuda_runtime.h>

#define NB    16384
#define NSTEP 100
#define DTC   0.1f

__global__ __launch_bounds__(128) void ukf_linear_kernel(
    const float* __restrict__ meas,    // [B,2,100]
    const float* __restrict__ state0,  // [B,4]
    const float* __restrict__ cov0,    // [B,4,4]
    const float* __restrict__ ctrl,    // [B,100,2]
    const float* __restrict__ Qm,      // [4,4]
    const float* __restrict__ Rm,      // [2,2]
    float* __restrict__ preds,         // [B,2,100]
    float* __restrict__ states,        // [B,4,100]
    float* __restrict__ covs)          // [B,4,4,100]
{
    int b = blockIdx.x * blockDim.x + threadIdx.x;
    if (b >= NB) return;

    // ---- load per-filter state ----
    float x[4];
#pragma unroll
    for (int i = 0; i < 4; i++) x[i] = state0[(size_t)b * 4 + i];

    float P[4][4];
#pragma unroll
    for (int i = 0; i < 4; i++)
#pragma unroll
        for (int j = 0; j < 4; j++) P[i][j] = cov0[(size_t)b * 16 + i * 4 + j];

    // ---- broadcast constants ----
    float Q[4][4];
#pragma unroll
    for (int i = 0; i < 4; i++)
#pragma unroll
        for (int j = 0; j < 4; j++) Q[i][j] = Qm[i * 4 + j];
    const float R00 = Rm[0], R01 = Rm[1], R11 = Rm[3];

    const float* mrow = meas + (size_t)b * 2 * NSTEP;   // [m*100 + s]
    const float* crow = ctrl + (size_t)b * NSTEP * 2;   // [s*2 + c]
    float* pr = preds  + (size_t)b * 2 * NSTEP;
    float* st = states + (size_t)b * 4 * NSTEP;
    float* cv = covs   + (size_t)b * 16 * NSTEP;

    for (int s = 0; s < NSTEP; s++) {
        const float ux = crow[2 * s];
        const float uy = crow[2 * s + 1];

        // ---- predict mean: x_pred = M x + b(u)  (exact collapse of sigma mean) ----
        float xp[4];
        xp[0] = x[0] + DTC * x[2] + 0.5f * DTC * DTC * ux;
        xp[1] = x[1] + DTC * x[3] + 0.5f * DTC * DTC * uy;
        xp[2] = x[2] + DTC * ux;
        xp[3] = x[3] + DTC * uy;

        // ---- A = M P M^T  (== sum_i Wc dX dX^T, exactly, since motion is affine) ----
        float Bm[4][4];
#pragma unroll
        for (int j = 0; j < 4; j++) {
            Bm[0][j] = P[0][j] + DTC * P[2][j];
            Bm[1][j] = P[1][j] + DTC * P[3][j];
            Bm[2][j] = P[2][j];
            Bm[3][j] = P[3][j];
        }
        float A[4][4];
#pragma unroll
        for (int i = 0; i < 4; i++) {
            A[i][0] = Bm[i][0] + DTC * Bm[i][2];
            A[i][1] = Bm[i][1] + DTC * Bm[i][3];
            A[i][2] = Bm[i][2];
            A[i][3] = Bm[i][3];
        }
        // enforce exact symmetry (reference symmetrizes P each step)
#pragma unroll
        for (int i = 0; i < 4; i++)
#pragma unroll
            for (int j = i + 1; j < 4; j++) A[j][i] = A[i][j];

        // ---- S = A[:2,:2] + R  (no Q: dZ is built from Xf before Q is added) ----
        const float s00 = A[0][0] + R00;
        const float s01 = A[0][1] + R01;
        const float s11 = A[1][1] + R11;
        const float det  = s00 * s11 - s01 * s01;
        const float idet = 1.0f / det;
        const float is00 =  s11 * idet;
        const float is01 = -s01 * idet;
        const float is11 =  s00 * idet;

        // ---- K = Pxz S^{-1},  Pxz = A[:, :2] ----
        float K[4][2];
#pragma unroll
        for (int i = 0; i < 4; i++) {
            K[i][0] = A[i][0] * is00 + A[i][1] * is01;
            K[i][1] = A[i][0] * is01 + A[i][1] * is11;
        }

        // ---- update mean ----
        const float z0 = mrow[s];
        const float z1 = mrow[NSTEP + s];
        const float in0 = z0 - xp[0];
        const float in1 = z1 - xp[1];
        float xn[4];
#pragma unroll
        for (int i = 0; i < 4; i++)
            xn[i] = xp[i] + K[i][0] * in0 + K[i][1] * in1;

        // ---- P_new = (A + Q) - K S K^T, symmetric by construction ----
        float KS0[4], KS1[4];
#pragma unroll
        for (int i = 0; i < 4; i++) {
            KS0[i] = K[i][0] * s00 + K[i][1] * s01;
            KS1[i] = K[i][0] * s01 + K[i][1] * s11;
        }
        float Pn[4][4];
#pragma unroll
        for (int i = 0; i < 4; i++)
#pragma unroll
            for (int j = i; j < 4; j++) {
                float v = A[i][j] + Q[i][j] - (KS0[i] * K[j][0] + KS1[i] * K[j][1]);
                Pn[i][j] = v;
                Pn[j][i] = v;
            }

        // ---- outputs (step index is the fastest-varying axis) ----
        pr[s]         = xp[0];   // z_pred = H x_pred
        pr[NSTEP + s] = xp[1];
#pragma unroll
        for (int i = 0; i < 4; i++) st[i * NSTEP + s] = xn[i];
#pragma unroll
        for (int i = 0; i < 4; i++)
#pragma unroll
            for (int j = 0; j < 4; j++) cv[(i * 4 + j) * NSTEP + s] = Pn[i][j];

        // ---- carry ----
#pragma unroll
        for (int i = 0; i < 4; i++) x[i] = xn[i];
#pragma unroll
        for (int i = 0; i < 4; i++)
#pragma unroll
            for (int j = 0; j < 4; j++) P[i][j] = Pn[i][j];
    }
}

extern "C" void kernel_launch(void* const* d_in, const int* in_sizes, int n_in,
                              void* d_out, int out_size)
{
    const float* meas  = (const float*)d_in[0];
    const float* state = (const float*)d_in[1];
    const float* cov   = (const float*)d_in[2];
    const float* ctrl  = (const float*)d_in[3];
    const float* Q     = (const float*)d_in[4];
    const float* R     = (const float*)d_in[5];

    float* out    = (float*)d_out;
    float* preds  = out;                                   // 16384*2*100
    float* states = preds  + (size_t)NB * 2 * NSTEP;       // 16384*4*100
    float* covs   = states + (size_t)NB * 4 * NSTEP;       // 16384*16*100

    ukf_linear_kernel<<<NB / 128, 128>>>(meas, state, cov, ctrl, Q, R,
                                         preds, states, covs);
}

// round 2
// speedup vs baseline: 2.9622x; 2.9622x over previous
#include <cuda_runtime.h>

#define NB    16384
#define NSTEP 100
#define DTC   0.1f
#define CH    8           // steps staged per chunk
#define SPAD  132         // padded filter stride in smem words (conflict-free)
#define SMEM_BYTES (22 * CH * SPAD * 4)

// ---------------------------------------------------------------------------
// One exact-collapsed UKF step (affine motion => linear KF), staging the 22
// output values into shared memory at [row][s'][tid] (stride SPAD).
// ---------------------------------------------------------------------------
__device__ __forceinline__ void ukf_step(
    float x[4], float P[4][4], const float Q[4][4],
    float R00, float R01, float R11,
    float ux, float uy, float z0, float z1,
    float* sb, int sp, int tid)
{
    float xp[4];
    xp[0] = x[0] + DTC * x[2] + 0.5f * DTC * DTC * ux;
    xp[1] = x[1] + DTC * x[3] + 0.5f * DTC * DTC * uy;
    xp[2] = x[2] + DTC * ux;
    xp[3] = x[3] + DTC * uy;

    // A = M P M^T  (exact collapse of the weighted sigma outer products)
    float Bm[4][4];
#pragma unroll
    for (int j = 0; j < 4; j++) {
        Bm[0][j] = P[0][j] + DTC * P[2][j];
        Bm[1][j] = P[1][j] + DTC * P[3][j];
        Bm[2][j] = P[2][j];
        Bm[3][j] = P[3][j];
    }
    float A[4][4];
#pragma unroll
    for (int i = 0; i < 4; i++) {
        A[i][0] = Bm[i][0] + DTC * Bm[i][2];
        A[i][1] = Bm[i][1] + DTC * Bm[i][3];
        A[i][2] = Bm[i][2];
        A[i][3] = Bm[i][3];
    }
#pragma unroll
    for (int i = 0; i < 4; i++)
#pragma unroll
        for (int j = i + 1; j < 4; j++) A[j][i] = A[i][j];

    // S = A[:2,:2] + R ; 2x2 inverse
    const float s00 = A[0][0] + R00;
    const float s01 = A[0][1] + R01;
    const float s11 = A[1][1] + R11;
    const float idet = 1.0f / (s00 * s11 - s01 * s01);
    const float is00 =  s11 * idet;
    const float is01 = -s01 * idet;
    const float is11 =  s00 * idet;

    float K[4][2];
#pragma unroll
    for (int i = 0; i < 4; i++) {
        K[i][0] = A[i][0] * is00 + A[i][1] * is01;
        K[i][1] = A[i][0] * is01 + A[i][1] * is11;
    }

    const float in0 = z0 - xp[0];
    const float in1 = z1 - xp[1];
    float xn[4];
#pragma unroll
    for (int i = 0; i < 4; i++) xn[i] = xp[i] + K[i][0] * in0 + K[i][1] * in1;

    float KS0[4], KS1[4];
#pragma unroll
    for (int i = 0; i < 4; i++) {
        KS0[i] = K[i][0] * s00 + K[i][1] * s01;
        KS1[i] = K[i][0] * s01 + K[i][1] * s11;
    }
    float Pn[4][4];
#pragma unroll
    for (int i = 0; i < 4; i++)
#pragma unroll
        for (int j = i; j < 4; j++) {
            float v = A[i][j] + Q[i][j] - (KS0[i] * K[j][0] + KS1[i] * K[j][1]);
            Pn[i][j] = v;
            Pn[j][i] = v;
        }

    // stage the 22 outputs: rows 0-1 preds, 2-5 states, 6-21 covs
    sb[(0 * CH + sp) * SPAD + tid] = xp[0];
    sb[(1 * CH + sp) * SPAD + tid] = xp[1];
#pragma unroll
    for (int i = 0; i < 4; i++) sb[((2 + i) * CH + sp) * SPAD + tid] = xn[i];
#pragma unroll
    for (int i = 0; i < 4; i++)
#pragma unroll
        for (int j = 0; j < 4; j++)
            sb[((6 + i * 4 + j) * CH + sp) * SPAD + tid] = Pn[i][j];

    // carry
#pragma unroll
    for (int i = 0; i < 4; i++) x[i] = xn[i];
#pragma unroll
    for (int i = 0; i < 4; i++)
#pragma unroll
        for (int j = 0; j < 4; j++) P[i][j] = Pn[i][j];
}

// ---------------------------------------------------------------------------
// Sector-packed flush: thread t = (f = t>>1, h = t&1). A warp writes 16
// filters x 2 halves = 16 fully-packed 32B sectors per row.
// ---------------------------------------------------------------------------
__device__ __forceinline__ void flush8(
    const float* sb, float* preds, float* states, float* covs,
    int blk, int tid, int s0)
{
    const int h  = tid & 1;
    const int f0 = tid >> 1;
#pragma unroll
    for (int p = 0; p < 2; p++) {
        const int f  = f0 + 64 * p;
        const int gb = blk * 128 + f;
        float* pp = preds  + (size_t)gb * 200  + s0 + 4 * h;
        float* ps = states + (size_t)gb * 400  + s0 + 4 * h;
        float* pc = covs   + (size_t)gb * 1600 + s0 + 4 * h;
#pragma unroll
        for (int r = 0; r < 22; r++) {
            const float* s_ = sb + (r * CH + 4 * h) * SPAD + f;
            float4 v = make_float4(s_[0], s_[SPAD], s_[2 * SPAD], s_[3 * SPAD]);
            float* dst = (r < 2) ? (pp + r * 100)
                       : (r < 6) ? (ps + (r - 2) * 100)
                                 : (pc + (r - 6) * 100);
            *reinterpret_cast<float4*>(dst) = v;
        }
    }
}

__global__ __launch_bounds__(128) void ukf_kernel(
    const float* __restrict__ meas,    // [B,2,100]
    const float* __restrict__ state0,  // [B,4]
    const float* __restrict__ cov0,    // [B,4,4]
    const float* __restrict__ ctrl,    // [B,100,2]
    const float* __restrict__ Qm,      // [4,4]
    const float* __restrict__ Rm,      // [2,2]
    float* __restrict__ preds, float* __restrict__ states, float* __restrict__ covs)
{
    extern __shared__ float sb[];
    const int tid = threadIdx.x;
    const int b   = blockIdx.x * 128 + tid;

    // per-filter state (vectorized loads)
    float x[4], P[4][4], Q[4][4];
    {
        float4 xv = *reinterpret_cast<const float4*>(state0 + (size_t)b * 4);
        x[0] = xv.x; x[1] = xv.y; x[2] = xv.z; x[3] = xv.w;
#pragma unroll
        for (int i = 0; i < 4; i++) {
            float4 pv = *reinterpret_cast<const float4*>(cov0 + (size_t)b * 16 + i * 4);
            P[i][0] = pv.x; P[i][1] = pv.y; P[i][2] = pv.z; P[i][3] = pv.w;
        }
#pragma unroll
        for (int i = 0; i < 4; i++)
#pragma unroll
            for (int j = 0; j < 4; j++) Q[i][j] = Qm[i * 4 + j];
    }
    const float R00 = Rm[0], R01 = Rm[1], R11 = Rm[3];

    const float* mrow = meas + (size_t)b * 200;
    const float* crow = ctrl + (size_t)b * 200;

    // double-buffered input prefetch (registers)
    float4 nb[8];
    {
        const float4* pa = reinterpret_cast<const float4*>(mrow);
        const float4* pb = reinterpret_cast<const float4*>(mrow + 100);
        const float4* pc = reinterpret_cast<const float4*>(crow);
        nb[0] = pa[0]; nb[1] = pa[1];
        nb[2] = pb[0]; nb[3] = pb[1];
        nb[4] = pc[0]; nb[5] = pc[1]; nb[6] = pc[2]; nb[7] = pc[3];
    }

    for (int ch = 0; ch < 12; ch++) {
        // unpack current chunk inputs
        float ma[8], mbv[8], cc[16];
        ma[0]=nb[0].x; ma[1]=nb[0].y; ma[2]=nb[0].z; ma[3]=nb[0].w;
        ma[4]=nb[1].x; ma[5]=nb[1].y; ma[6]=nb[1].z; ma[7]=nb[1].w;
        mbv[0]=nb[2].x; mbv[1]=nb[2].y; mbv[2]=nb[2].z; mbv[3]=nb[2].w;
        mbv[4]=nb[3].x; mbv[5]=nb[3].y; mbv[6]=nb[3].z; mbv[7]=nb[3].w;
        cc[0]=nb[4].x; cc[1]=nb[4].y; cc[2]=nb[4].z; cc[3]=nb[4].w;
        cc[4]=nb[5].x; cc[5]=nb[5].y; cc[6]=nb[5].z; cc[7]=nb[5].w;
        cc[8]=nb[6].x; cc[9]=nb[6].y; cc[10]=nb[6].z; cc[11]=nb[6].w;
        cc[12]=nb[7].x; cc[13]=nb[7].y; cc[14]=nb[7].z; cc[15]=nb[7].w;

        // prefetch next chunk (chunk 12 is the 4-step tail: load only 1st halves)
        {
            const int s0n = (ch + 1) * CH;
            const float4* pa = reinterpret_cast<const float4*>(mrow + s0n);
            const float4* pb = reinterpret_cast<const float4*>(mrow + 100 + s0n);
            const float4* pc = reinterpret_cast<const float4*>(crow + 2 * s0n);
            nb[0] = pa[0]; nb[2] = pb[0]; nb[4] = pc[0]; nb[5] = pc[1];
            if (ch + 1 < 12) { nb[1] = pa[1]; nb[3] = pb[1]; nb[6] = pc[2]; nb[7] = pc[3]; }
        }

#pragma unroll
        for (int sp = 0; sp < CH; sp++)
            ukf_step(x, P, Q, R00, R01, R11,
                     cc[2 * sp], cc[2 * sp + 1], ma[sp], mbv[sp], sb, sp, tid);

        __syncthreads();
        flush8(sb, preds, states, covs, blockIdx.x, tid, ch * CH);
        __syncthreads();
    }

    // ---- tail: 4 steps at s0 = 96 ----
    {
        float ma[4], mbv[4], cc[8];
        ma[0]=nb[0].x; ma[1]=nb[0].y; ma[2]=nb[0].z; ma[3]=nb[0].w;
        mbv[0]=nb[2].x; mbv[1]=nb[2].y; mbv[2]=nb[2].z; mbv[3]=nb[2].w;
        cc[0]=nb[4].x; cc[1]=nb[4].y; cc[2]=nb[4].z; cc[3]=nb[4].w;
        cc[4]=nb[5].x; cc[5]=nb[5].y; cc[6]=nb[5].z; cc[7]=nb[5].w;

#pragma unroll
        for (int sp = 0; sp < 4; sp++)
            ukf_step(x, P, Q, R00, R01, R11,
                     cc[2 * sp], cc[2 * sp + 1], ma[sp], mbv[sp], sb, sp, tid);

        __syncthreads();
        const int h  = tid & 1;
        const int f0 = tid >> 1;
        if (h == 0) {
#pragma unroll
            for (int p = 0; p < 2; p++) {
                const int f  = f0 + 64 * p;
                const int gb = blockIdx.x * 128 + f;
                float* pp = preds  + (size_t)gb * 200  + 96;
                float* ps = states + (size_t)gb * 400  + 96;
                float* pc = covs   + (size_t)gb * 1600 + 96;
#pragma unroll
                for (int r = 0; r < 22; r++) {
                    const float* s_ = sb + (r * CH) * SPAD + f;
                    float4 v = make_float4(s_[0], s_[SPAD], s_[2 * SPAD], s_[3 * SPAD]);
                    float* dst = (r < 2) ? (pp + r * 100)
                               : (r < 6) ? (ps + (r - 2) * 100)
                                         : (pc + (r - 6) * 100);
                    *reinterpret_cast<float4*>(dst) = v;
                }
            }
        }
    }
}

extern "C" void kernel_launch(void* const* d_in, const int* in_sizes, int n_in,
                              void* d_out, int out_size)
{
    const float* meas  = (const float*)d_in[0];
    const float* state = (const float*)d_in[1];
    const float* cov   = (const float*)d_in[2];
    const float* ctrl  = (const float*)d_in[3];
    const float* Q     = (const float*)d_in[4];
    const float* R     = (const float*)d_in[5];

    float* out    = (float*)d_out;
    float* preds  = out;                              // 16384*2*100
    float* states = preds  + (size_t)NB * 2 * NSTEP;  // 16384*4*100
    float* covs   = states + (size_t)NB * 4 * NSTEP;  // 16384*16*100

    static int smem_set = 0;
    if (!smem_set) {
        cudaFuncSetAttribute(ukf_kernel,
                             cudaFuncAttributeMaxDynamicSharedMemorySize, SMEM_BYTES);
        smem_set = 1;
    }

    ukf_kernel<<<NB / 128, 128, SMEM_BYTES>>>(meas, state, cov, ctrl, Q, R,
                                              preds, states, covs);
}